// round 15
// baseline (speedup 1.0000x reference)
// SpatialAttention — R15: proj split to 64x64 tiles / 768 CTAs (tail fix); attn frozen (R13).
#include <cuda_runtime.h>
#include <cuda_bf16.h>
#include <stdint.h>

#define NB  32
#define IDF 768
#define CDF 768
#define QL  1024
#define SL  128

// bf16 split scratch
__device__ __align__(128) __nv_bfloat16 g_w_hi[(size_t)IDF * CDF];
__device__ __align__(128) __nv_bfloat16 g_w_lo[(size_t)IDF * CDF];
__device__ __align__(128) __nv_bfloat16 g_ctxT_hi[(size_t)NB * SL * CDF];
__device__ __align__(128) __nv_bfloat16 g_ctxT_lo[(size_t)NB * SL * CDF];
__device__ __align__(128) __nv_bfloat16 g_sis_hi[(size_t)NB * IDF * SL];   // [b][i][s]
__device__ __align__(128) __nv_bfloat16 g_sis_lo[(size_t)NB * IDF * SL];
__device__ __align__(128) __nv_bfloat16 g_ssi_hi[(size_t)NB * SL * IDF];   // [b][s][i]
__device__ __align__(128) __nv_bfloat16 g_ssi_lo[(size_t)NB * SL * IDF];

__device__ __forceinline__ uint32_t smem_u32(const void* p) {
    uint32_t a;
    asm("{ .reg .u64 t; cvta.to.shared.u64 t, %1; cvt.u32.u64 %0, t; }" : "=r"(a) : "l"(p));
    return a;
}
#define SW64(x) ((x) ^ (((x) >> 3) & 0x30))

__device__ __forceinline__ void split2(float v, __nv_bfloat16& h, __nv_bfloat16& l) {
    h = __float2bfloat16(v);
    l = __float2bfloat16(v - __bfloat162float(h));
}
__device__ __forceinline__ uint32_t pack_bf2(__nv_bfloat16 a, __nv_bfloat16 b) {
    __nv_bfloat162 p; p.x = a; p.y = b;
    return *reinterpret_cast<uint32_t*>(&p);
}

#define CP_A16(dst, src) \
    asm volatile("cp.async.cg.shared.global [%0], [%1], 16;" :: "r"(dst), "l"(src))
#define CP_COMMIT() asm volatile("cp.async.commit_group;" ::: "memory")
#define CP_WAIT0()  asm volatile("cp.async.wait_group 0;" ::: "memory")
#define CP_WAIT1()  asm volatile("cp.async.wait_group 1;" ::: "memory")

// k=32 bf16 K-major tile [ROWS x 64B], SW64-swizzled, via cp.async. gstride bytes.
template <int ROWS>
__device__ __forceinline__ void cp64(uint32_t sbase, const __nv_bfloat16* g,
                                     int gstride, int tid) {
#pragma unroll
    for (int p = 0; p < ROWS / 64; p++) {
        int idx = tid + p * 256;
        int row = idx >> 2, c = (idx & 3) << 4;
        CP_A16(sbase + SW64((uint32_t)(row * 64 + c)),
               reinterpret_cast<const char*>(g) + (size_t)row * gstride + c);
    }
}

// x4 ldmatrix of a 16x16 bf16 block at (row0, kbyte) in a SW64 [r][64B] tile.
__device__ __forceinline__ void ldm4_64(uint32_t r[4], uint32_t base, int row0,
                                        int kbyte, int lane) {
    int row = row0 + (lane & 15);
    int col = kbyte + ((lane >> 4) << 4);
    uint32_t addr = base + SW64((uint32_t)(row * 64 + col));
    asm volatile("ldmatrix.sync.aligned.m8n8.x4.shared.b16 {%0,%1,%2,%3}, [%4];"
                 : "=r"(r[0]), "=r"(r[1]), "=r"(r[2]), "=r"(r[3]) : "r"(addr));
}

__device__ __forceinline__ void mma16(float c[4], const uint32_t a[4], const uint32_t b[2]) {
    asm volatile("mma.sync.aligned.m16n8k16.row.col.f32.bf16.bf16.f32 "
                 "{%0,%1,%2,%3}, {%4,%5,%6,%7}, {%8,%9}, {%0,%1,%2,%3};"
                 : "+f"(c[0]), "+f"(c[1]), "+f"(c[2]), "+f"(c[3])
                 : "r"(a[0]), "r"(a[1]), "r"(a[2]), "r"(a[3]), "r"(b[0]), "r"(b[1]));
}

// One k=32 chunk of a 32(m) x 32(n) warp tile, split-bf16 (attn kernel).
__device__ __forceinline__ void gemm_chunk(float acc[2][4][4],
                                           uint32_t aHi, uint32_t aLo,
                                           uint32_t bHi, uint32_t bLo,
                                           int m0, int n0, int lane) {
#pragma unroll
    for (int k = 0; k < 2; k++) {
        const int kb = k * 32;
        uint32_t ah[2][4], al[2][4], bh[4][2], bl[4][2], t[4];
#pragma unroll
        for (int m = 0; m < 2; m++) {
            ldm4_64(ah[m], aHi, m0 + m * 16, kb, lane);
            ldm4_64(al[m], aLo, m0 + m * 16, kb, lane);
        }
#pragma unroll
        for (int j = 0; j < 2; j++) {
            ldm4_64(t, bHi, n0 + j * 16, kb, lane);
            bh[2 * j][0] = t[0]; bh[2 * j][1] = t[2];
            bh[2 * j + 1][0] = t[1]; bh[2 * j + 1][1] = t[3];
            ldm4_64(t, bLo, n0 + j * 16, kb, lane);
            bl[2 * j][0] = t[0]; bl[2 * j][1] = t[2];
            bl[2 * j + 1][0] = t[1]; bl[2 * j + 1][1] = t[3];
        }
#pragma unroll
        for (int m = 0; m < 2; m++)
#pragma unroll
            for (int n = 0; n < 4; n++) {
                mma16(acc[m][n], ah[m], bh[n]);
                mma16(acc[m][n], ah[m], bl[n]);
                mma16(acc[m][n], al[m], bh[n]);
            }
    }
}

// One k=32 chunk of a 32(m) x 16(n) warp tile, split-bf16 (proj kernel).
__device__ __forceinline__ void gemm_chunk16(float acc[2][2][4],
                                             uint32_t aHi, uint32_t aLo,
                                             uint32_t bHi, uint32_t bLo,
                                             int m0, int n0, int lane) {
#pragma unroll
    for (int k = 0; k < 2; k++) {
        const int kb = k * 32;
        uint32_t ah[2][4], al[2][4], bh[2][2], bl[2][2], t[4];
#pragma unroll
        for (int m = 0; m < 2; m++) {
            ldm4_64(ah[m], aHi, m0 + m * 16, kb, lane);
            ldm4_64(al[m], aLo, m0 + m * 16, kb, lane);
        }
        ldm4_64(t, bHi, n0, kb, lane);
        bh[0][0] = t[0]; bh[0][1] = t[2];
        bh[1][0] = t[1]; bh[1][1] = t[3];
        ldm4_64(t, bLo, n0, kb, lane);
        bl[0][0] = t[0]; bl[0][1] = t[2];
        bl[1][0] = t[1]; bl[1][1] = t[3];
#pragma unroll
        for (int m = 0; m < 2; m++)
#pragma unroll
            for (int n = 0; n < 2; n++) {
                mma16(acc[m][n], ah[m], bh[n]);
                mma16(acc[m][n], ah[m], bl[n]);
                mma16(acc[m][n], al[m], bh[n]);
            }
    }
}

#define ZERO_ACC(acc) \
    { _Pragma("unroll") for (int m = 0; m < 2; m++) \
      _Pragma("unroll") for (int n = 0; n < 4; n++) \
      _Pragma("unroll") for (int v = 0; v < 4; v++) acc[m][n][v] = 0.f; }

#define PSTAGE 16384     // proj: A hi/lo 4KB+4KB, B hi/lo 4KB+4KB
#define BSTAGE 16384
#define NSTG   3
// attn smem: [0,49152) 3x16KB stages; [49152,73728) 3x8KB A-slots; [73728,106496) BATT
#define ASLOTOFF 49152
#define BATTOFF  73728
#define ATTN_SMEM 106496

// ---------------- fused prepass: conv_w (blocks < WCTAS) + trans_ctx ----------------
#define WCTAS 576   // 147456 float4 / 256
__global__ void prepass_kernel(const float* __restrict__ w, const float* __restrict__ ctx) {
    __shared__ float t[32][33];
    const int bid = blockIdx.x, tid = threadIdx.x;
    if (bid < WCTAS) {
        int i4 = bid * 256 + tid;
        float4 v = reinterpret_cast<const float4*>(w)[i4];
        __nv_bfloat16 h0, l0, h1, l1, h2, l2, h3, l3;
        split2(v.x, h0, l0); split2(v.y, h1, l1);
        split2(v.z, h2, l2); split2(v.w, h3, l3);
        reinterpret_cast<uint2*>(g_w_hi)[i4] = make_uint2(pack_bf2(h0, h1), pack_bf2(h2, h3));
        reinterpret_cast<uint2*>(g_w_lo)[i4] = make_uint2(pack_bf2(l0, l1), pack_bf2(l2, l3));
        return;
    }
    const int g = bid - WCTAS;
    const int b = g / 96, rem = g % 96;
    const int c0 = (rem >> 2) * 32, s0 = (rem & 3) * 32;
    const int x = tid & 31, y = tid >> 5;      // 32 x 8
#pragma unroll
    for (int r = 0; r < 32; r += 8)
        t[y + r][x] = ctx[((size_t)b * CDF + c0 + y + r) * SL + s0 + x];
    __syncthreads();
#pragma unroll
    for (int r = 0; r < 32; r += 8) {
        size_t o = ((size_t)b * SL + s0 + y + r) * CDF + c0 + x;
        __nv_bfloat16 h, l; split2(t[x][y + r], h, l);
        g_ctxT_hi[o] = h; g_ctxT_lo[o] = l;
    }
}

// ---------------- proj: 64(o) x 64(s) tiles, grid (12, 2, 32) ----------------
__global__ void __launch_bounds__(256, 2) proj_kernel() {
    extern __shared__ __align__(1024) char smem[];
    const int tid = threadIdx.x, lane = tid & 31, wp = tid >> 5;
    const int wm = wp & 1, wn = wp >> 1;                     // warps 2(m) x 4(n), tile 32x16
    const int b = blockIdx.z, o0 = blockIdx.x * 64, s0 = blockIdx.y * 64;
    uint32_t sb = smem_u32(smem);
    float* Cb = reinterpret_cast<float*>(smem);              // [64][65] fp32, aliases stages

    const __nv_bfloat16* wh_base = g_w_hi + (size_t)o0 * CDF;
    const __nv_bfloat16* wl_base = g_w_lo + (size_t)o0 * CDF;
    const __nv_bfloat16* ch_base = g_ctxT_hi + ((size_t)b * SL + s0) * CDF;
    const __nv_bfloat16* cl_base = g_ctxT_lo + ((size_t)b * SL + s0) * CDF;

    float acc[2][2][4];
#pragma unroll
    for (int m = 0; m < 2; m++)
#pragma unroll
        for (int n = 0; n < 2; n++)
#pragma unroll
            for (int v = 0; v < 4; v++) acc[m][n][v] = 0.f;

    auto issue = [&](int j) {
        uint32_t S = sb + (j % NSTG) * PSTAGE;
        cp64<64>(S,         wh_base + j * 32, CDF * 2, tid);
        cp64<64>(S + 4096,  wl_base + j * 32, CDF * 2, tid);
        cp64<64>(S + 8192,  ch_base + j * 32, CDF * 2, tid);
        cp64<64>(S + 12288, cl_base + j * 32, CDF * 2, tid);
        CP_COMMIT();
    };
    issue(0); issue(1);
#pragma unroll 1
    for (int j = 0; j < 24; j++) {
        if (j < 23) CP_WAIT1(); else CP_WAIT0();
        __syncthreads();
        if (j + 2 < 24) issue(j + 2);
        uint32_t S = sb + (j % NSTG) * PSTAGE;
        gemm_chunk16(acc, S, S + 4096, S + 8192, S + 12288, wm * 32, wn * 16, lane);
    }
    __syncthreads();

    // Epilogue pass 1: sis [b][i][s] DIRECT from fragments + Cb stage for ssi.
    {
        __nv_bfloat16* sh = g_sis_hi + ((size_t)b * IDF + o0) * SL + s0;
        __nv_bfloat16* sl = g_sis_lo + ((size_t)b * IDF + o0) * SL + s0;
#pragma unroll
        for (int m = 0; m < 2; m++)
#pragma unroll
            for (int h = 0; h < 2; h++) {
                const int o = wm * 32 + m * 16 + (lane >> 2) + h * 8;
#pragma unroll
                for (int n = 0; n < 2; n++) {
                    float v0 = acc[m][n][h * 2 + 0];
                    float v1 = acc[m][n][h * 2 + 1];
                    const int s = wn * 16 + n * 8 + (lane & 3) * 2;
                    Cb[o * 65 + s]     = v0;
                    Cb[o * 65 + s + 1] = v1;
                    __nv_bfloat16 h0, l0, h1, l1;
                    split2(v0, h0, l0); split2(v1, h1, l1);
                    *reinterpret_cast<uint32_t*>(sh + (size_t)o * SL + s) = pack_bf2(h0, h1);
                    *reinterpret_cast<uint32_t*>(sl + (size_t)o * SL + s) = pack_bf2(l0, l1);
                }
            }
    }
    __syncthreads();

    // Epilogue pass 2: ssi [b][s][i] via Cb transpose read. 256 thr: s=tid/4, 16 o's.
    {
        const int s = tid >> 2, oq = (tid & 3) * 16;
        uint32_t uh[8], ul[8];
#pragma unroll
        for (int m = 0; m < 8; m++) {
            float v0 = Cb[(oq + 2 * m) * 65 + s];
            float v1 = Cb[(oq + 2 * m + 1) * 65 + s];
            __nv_bfloat16 h0, l0, h1, l1; split2(v0, h0, l0); split2(v1, h1, l1);
            uh[m] = pack_bf2(h0, h1); ul[m] = pack_bf2(l0, l1);
        }
        size_t off = ((size_t)b * SL + s0 + s) * IDF + o0 + oq;
#pragma unroll
        for (int m = 0; m < 2; m++) {
            reinterpret_cast<uint4*>(g_ssi_hi + off)[m] =
                make_uint4(uh[4 * m], uh[4 * m + 1], uh[4 * m + 2], uh[4 * m + 3]);
            reinterpret_cast<uint4*>(g_ssi_lo + off)[m] =
                make_uint4(ul[4 * m], ul[4 * m + 1], ul[4 * m + 2], ul[4 * m + 3]);
        }
    }
}

// ---------------- fused attention: register softmax (R13, frozen) ----------------
__global__ void __launch_bounds__(256, 2) attn_kernel(const float* __restrict__ input,
                                                      const int* __restrict__ mask,
                                                      float* __restrict__ wc,
                                                      float* __restrict__ aout) {
    extern __shared__ __align__(1024) char smem[];
    __shared__ float red[64][4];
    const int tid = threadIdx.x, lane = tid & 31, wp = tid >> 5;
    const int b = blockIdx.y, q0 = blockIdx.x * 64;
    uint32_t sb = smem_u32(smem);
    const uint32_t ASLOT = sb + ASLOTOFF;
    const uint32_t BATT  = sb + BATTOFF;

    const int wm1 = wp & 1, wn1 = wp >> 1;          // D 64(q) x 128(s)
    const __nv_bfloat16* sh_base = g_ssi_hi + (size_t)b * SL * IDF;
    const __nv_bfloat16* sl_base = g_ssi_lo + (size_t)b * SL * IDF;
    const int cq = tid & 63, cig = tid >> 6;
    const float* cbase = input + ((size_t)b * IDF + cig * 8) * QL + q0 + cq;
    const uint32_t coff = SW64((uint32_t)(cq * 64 + cig * 16));

    float acc[2][4][4];
    ZERO_ACC(acc);
    float cvt[8];

    auto ldgA = [&](int j) {
        const float* s = cbase + (size_t)(j * 32) * QL;
#pragma unroll
        for (int m = 0; m < 8; m++) cvt[m] = s[(size_t)m * QL];
    };
    auto stsA = [&](int j) {
        uint32_t h[4], l[4];
#pragma unroll
        for (int m = 0; m < 4; m++) {
            __nv_bfloat16 h0, l0, h1, l1;
            split2(cvt[2 * m], h0, l0); split2(cvt[2 * m + 1], h1, l1);
            h[m] = pack_bf2(h0, h1); l[m] = pack_bf2(l0, l1);
        }
        uint32_t A = ASLOT + (j % 3) * 8192;
        asm volatile("st.shared.v4.b32 [%0], {%1,%2,%3,%4};"
                     :: "r"(A + coff), "r"(h[0]), "r"(h[1]), "r"(h[2]), "r"(h[3]));
        asm volatile("st.shared.v4.b32 [%0], {%1,%2,%3,%4};"
                     :: "r"(A + 4096 + coff), "r"(l[0]), "r"(l[1]), "r"(l[2]), "r"(l[3]));
    };
    auto issueB = [&](int j) {
        uint32_t S = sb + (j % NSTG) * BSTAGE;
        cp64<128>(S,        sh_base + j * 32, IDF * 2, tid);
        cp64<128>(S + 8192, sl_base + j * 32, IDF * 2, tid);
        CP_COMMIT();
    };

    ldgA(0); stsA(0); ldgA(1);
    issueB(0); issueB(1);
#pragma unroll 1
    for (int j = 0; j < 24; j++) {
        if (j + 1 < 24) stsA(j + 1);
        if (j + 2 < 24) ldgA(j + 2);
        if (j < 23) CP_WAIT1(); else CP_WAIT0();
        __syncthreads();
        if (j + 2 < 24) issueB(j + 2);
        uint32_t S = sb + (j % NSTG) * BSTAGE;
        uint32_t A = ASLOT + (j % 3) * 8192;
        gemm_chunk(acc, A, A + 4096, S, S + 8192, wm1 * 32, wn1 * 32, lane);
    }
    __syncthreads();

    const __nv_bfloat16* sish_base = g_sis_hi + (size_t)b * IDF * SL;
    const __nv_bfloat16* sisl_base = g_sis_lo + (size_t)b * IDF * SL;
    auto issue3 = [&](int c) {
        int t = c >> 2, kc = c & 3;
        uint32_t S = sb + (c % NSTG) * BSTAGE;
        const size_t base = (size_t)t * 128 * SL + kc * 32;
        cp64<128>(S,        sish_base + base, SL * 2, tid);
        cp64<128>(S + 8192, sisl_base + base, SL * 2, tid);
        CP_COMMIT();
    };
    issue3(0); issue3(1);

    // phase 2: softmax in registers
    {
        float mp[8];
#pragma unroll
        for (int n = 0; n < 4; n++)
#pragma unroll
            for (int vi = 0; vi < 2; vi++)
                mp[n * 2 + vi] = -10000.0f *
                    (float)mask[b * SL + wn1 * 32 + n * 8 + (lane & 3) * 2 + vi];

        float mx4[4];
#pragma unroll
        for (int mi = 0; mi < 2; mi++)
#pragma unroll
            for (int h = 0; h < 2; h++) {
                float mx = -1e30f;
#pragma unroll
                for (int n = 0; n < 4; n++)
#pragma unroll
                    for (int vi = 0; vi < 2; vi++) {
                        int v = h * 2 + vi;
                        acc[mi][n][v] += mp[n * 2 + vi];
                        mx = fmaxf(mx, acc[mi][n][v]);
                    }
                mx4[mi * 2 + h] = mx;
            }
#pragma unroll
        for (int r = 0; r < 4; r++) {
            mx4[r] = fmaxf(mx4[r], __shfl_xor_sync(0xffffffffu, mx4[r], 1));
            mx4[r] = fmaxf(mx4[r], __shfl_xor_sync(0xffffffffu, mx4[r], 2));
        }
        if ((lane & 3) == 0)
#pragma unroll
            for (int r = 0; r < 4; r++)
                red[wm1 * 32 + (r >> 1) * 16 + (lane >> 2) + (r & 1) * 8][wn1] = mx4[r];
        __syncthreads();
#pragma unroll
        for (int r = 0; r < 4; r++) {
            const float* rr = red[wm1 * 32 + (r >> 1) * 16 + (lane >> 2) + (r & 1) * 8];
            mx4[r] = fmaxf(fmaxf(rr[0], rr[1]), fmaxf(rr[2], rr[3]));
        }
        __syncthreads();

        float sm4[4];
#pragma unroll
        for (int mi = 0; mi < 2; mi++)
#pragma unroll
            for (int h = 0; h < 2; h++) {
                float sum = 0.f;
#pragma unroll
                for (int n = 0; n < 4; n++)
#pragma unroll
                    for (int vi = 0; vi < 2; vi++) {
                        int v = h * 2 + vi;
                        float e = __expf(acc[mi][n][v] - mx4[mi * 2 + h]);
                        acc[mi][n][v] = e;
                        sum += e;
                    }
                sm4[mi * 2 + h] = sum;
            }
#pragma unroll
        for (int r = 0; r < 4; r++) {
            sm4[r] += __shfl_xor_sync(0xffffffffu, sm4[r], 1);
            sm4[r] += __shfl_xor_sync(0xffffffffu, sm4[r], 2);
        }
        if ((lane & 3) == 0)
#pragma unroll
            for (int r = 0; r < 4; r++)
                red[wm1 * 32 + (r >> 1) * 16 + (lane >> 2) + (r & 1) * 8][wn1] = sm4[r];
        __syncthreads();
#pragma unroll
        for (int r = 0; r < 4; r++) {
            const float* rr = red[wm1 * 32 + (r >> 1) * 16 + (lane >> 2) + (r & 1) * 8];
            sm4[r] = 1.0f / (rr[0] + rr[1] + rr[2] + rr[3]);
        }

        float* ao = aout + (size_t)b * SL * QL + q0;
        const uint32_t BH = BATT + wn1 * 8192, BL = BH + 4096;
#pragma unroll
        for (int mi = 0; mi < 2; mi++)
#pragma unroll
            for (int h = 0; h < 2; h++) {
                const float inv = sm4[mi * 2 + h];
                const int q = wm1 * 32 + mi * 16 + (lane >> 2) + h * 8;
#pragma unroll
                for (int n = 0; n < 4; n++) {
                    float e0 = acc[mi][n][h * 2 + 0] * inv;
                    float e1 = acc[mi][n][h * 2 + 1] * inv;
                    const int s0 = wn1 * 32 + n * 8 + (lane & 3) * 2;
                    ao[(size_t)s0 * QL + q]       = e0;
                    ao[(size_t)(s0 + 1) * QL + q] = e1;
                    __nv_bfloat16 h0, l0, h1, l1;
                    split2(e0, h0, l0); split2(e1, h1, l1);
                    uint32_t off = SW64((uint32_t)(q * 64 + (s0 & 31) * 2));
                    asm volatile("st.shared.b32 [%0], %1;"
                                 :: "r"(BH + off), "r"(pack_bf2(h0, h1)));
                    asm volatile("st.shared.b32 [%0], %1;"
                                 :: "r"(BL + off), "r"(pack_bf2(l0, l1)));
                }
            }
    }
    __syncthreads();

    // phase 3
    const int wm3 = wp >> 1, wn3 = wp & 1;          // D 128(i) x 64(q)
#pragma unroll 1
    for (int c = 0; c < 24; c++) {
        if (c < 23) CP_WAIT1(); else CP_WAIT0();
        __syncthreads();
        if (c + 2 < 24) issue3(c + 2);
        if ((c & 3) == 0) ZERO_ACC(acc);
        uint32_t S = sb + (c % NSTG) * BSTAGE;
        uint32_t BH = BATT + (c & 3) * 8192;
        gemm_chunk(acc, S, S + 8192, BH, BH + 4096, wm3 * 32, wn3 * 32, lane);
        if ((c & 3) == 3) {
            int t = c >> 2;
            float* w0 = wc + ((size_t)b * IDF + t * 128) * QL + q0;
#pragma unroll
            for (int m = 0; m < 2; m++)
#pragma unroll
                for (int n = 0; n < 4; n++) {
                    int r = wm3 * 32 + m * 16 + (lane >> 2);
                    int cc = wn3 * 32 + n * 8 + (lane & 3) * 2;
                    *reinterpret_cast<float2*>(w0 + (size_t)r * QL + cc) =
                        make_float2(acc[m][n][0], acc[m][n][1]);
                    *reinterpret_cast<float2*>(w0 + (size_t)(r + 8) * QL + cc) =
                        make_float2(acc[m][n][2], acc[m][n][3]);
                }
        }
    }
}

// ---------------------------------------------------------------------------
extern "C" void kernel_launch(void* const* d_in, const int* in_sizes, int n_in,
                              void* d_out, int out_size) {
    const float* input   = (const float*)d_in[0];
    const float* context = (const float*)d_in[1];
    const int*   mask    = (const int*)d_in[2];
    const float* w_conv  = (const float*)d_in[3];

    float* wc   = (float*)d_out;
    float* aout = wc + (size_t)NB * IDF * QL;

    prepass_kernel<<<WCTAS + NB * 96, 256>>>(w_conv, context);

    const int smem_proj = NSTG * PSTAGE;                    // 49152
    cudaFuncSetAttribute(proj_kernel, cudaFuncAttributeMaxDynamicSharedMemorySize,
                         smem_proj);
    proj_kernel<<<dim3(IDF / 64, 2, NB), 256, smem_proj>>>();

    cudaFuncSetAttribute(attn_kernel, cudaFuncAttributeMaxDynamicSharedMemorySize,
                         ATTN_SMEM);                        // 106496
    attn_kernel<<<dim3(QL / 64, NB), 256, ATTN_SMEM>>>(input, mask, wc, aout);
}

// round 16
// speedup vs baseline: 1.0194x; 1.0194x over previous
// SpatialAttention — R16: 32x64 warp tiles @ 128-thr CTAs (smem-BW fix), proj+attn.
#include <cuda_runtime.h>
#include <cuda_bf16.h>
#include <stdint.h>

#define NB  32
#define IDF 768
#define CDF 768
#define QL  1024
#define SL  128

__device__ __align__(128) __nv_bfloat16 g_w_hi[(size_t)IDF * CDF];
__device__ __align__(128) __nv_bfloat16 g_w_lo[(size_t)IDF * CDF];
__device__ __align__(128) __nv_bfloat16 g_ctxT_hi[(size_t)NB * SL * CDF];
__device__ __align__(128) __nv_bfloat16 g_ctxT_lo[(size_t)NB * SL * CDF];
__device__ __align__(128) __nv_bfloat16 g_sis_hi[(size_t)NB * IDF * SL];   // [b][i][s]
__device__ __align__(128) __nv_bfloat16 g_sis_lo[(size_t)NB * IDF * SL];
__device__ __align__(128) __nv_bfloat16 g_ssi_hi[(size_t)NB * SL * IDF];   // [b][s][i]
__device__ __align__(128) __nv_bfloat16 g_ssi_lo[(size_t)NB * SL * IDF];

__device__ __forceinline__ uint32_t smem_u32(const void* p) {
    uint32_t a;
    asm("{ .reg .u64 t; cvta.to.shared.u64 t, %1; cvt.u32.u64 %0, t; }" : "=r"(a) : "l"(p));
    return a;
}
#define SW64(x) ((x) ^ (((x) >> 3) & 0x30))

__device__ __forceinline__ void split2(float v, __nv_bfloat16& h, __nv_bfloat16& l) {
    h = __float2bfloat16(v);
    l = __float2bfloat16(v - __bfloat162float(h));
}
__device__ __forceinline__ uint32_t pack_bf2(__nv_bfloat16 a, __nv_bfloat16 b) {
    __nv_bfloat162 p; p.x = a; p.y = b;
    return *reinterpret_cast<uint32_t*>(&p);
}

#define CP_A16(dst, src) \
    asm volatile("cp.async.cg.shared.global [%0], [%1], 16;" :: "r"(dst), "l"(src))
#define CP_COMMIT() asm volatile("cp.async.commit_group;" ::: "memory")
#define CP_WAIT0()  asm volatile("cp.async.wait_group 0;" ::: "memory")
#define CP_WAIT1()  asm volatile("cp.async.wait_group 1;" ::: "memory")

// k=32 bf16 K-major tile [ROWS x 64B], SW64-swizzled, via cp.async.
template <int ROWS, int THREADS>
__device__ __forceinline__ void cp64(uint32_t sbase, const __nv_bfloat16* g,
                                     int gstride, int tid) {
#pragma unroll
    for (int p = 0; p < ROWS * 4 / THREADS; p++) {
        int idx = tid + p * THREADS;
        int row = idx >> 2, c = (idx & 3) << 4;
        CP_A16(sbase + SW64((uint32_t)(row * 64 + c)),
               reinterpret_cast<const char*>(g) + (size_t)row * gstride + c);
    }
}

__device__ __forceinline__ void ldm4_64(uint32_t r[4], uint32_t base, int row0,
                                        int kbyte, int lane) {
    int row = row0 + (lane & 15);
    int col = kbyte + ((lane >> 4) << 4);
    uint32_t addr = base + SW64((uint32_t)(row * 64 + col));
    asm volatile("ldmatrix.sync.aligned.m8n8.x4.shared.b16 {%0,%1,%2,%3}, [%4];"
                 : "=r"(r[0]), "=r"(r[1]), "=r"(r[2]), "=r"(r[3]) : "r"(addr));
}

__device__ __forceinline__ void mma16(float c[4], const uint32_t a[4], const uint32_t b[2]) {
    asm volatile("mma.sync.aligned.m16n8k16.row.col.f32.bf16.bf16.f32 "
                 "{%0,%1,%2,%3}, {%4,%5,%6,%7}, {%8,%9}, {%0,%1,%2,%3};"
                 : "+f"(c[0]), "+f"(c[1]), "+f"(c[2]), "+f"(c[3])
                 : "r"(a[0]), "r"(a[1]), "r"(a[2]), "r"(a[3]), "r"(b[0]), "r"(b[1]));
}

// One k=32 chunk of a 32(m) x 64(n) warp tile, split-bf16 (3 mmas per pair).
__device__ __forceinline__ void gemm64(float acc[2][8][4],
                                       uint32_t aHi, uint32_t aLo,
                                       uint32_t bHi, uint32_t bLo,
                                       int m0, int n0, int lane) {
#pragma unroll
    for (int k = 0; k < 2; k++) {
        const int kb = k * 32;
        uint32_t ah[2][4], al[2][4], bh[8][2], bl[8][2], t[4];
#pragma unroll
        for (int m = 0; m < 2; m++) {
            ldm4_64(ah[m], aHi, m0 + m * 16, kb, lane);
            ldm4_64(al[m], aLo, m0 + m * 16, kb, lane);
        }
#pragma unroll
        for (int j = 0; j < 4; j++) {
            ldm4_64(t, bHi, n0 + j * 16, kb, lane);
            bh[2 * j][0] = t[0]; bh[2 * j][1] = t[2];
            bh[2 * j + 1][0] = t[1]; bh[2 * j + 1][1] = t[3];
            ldm4_64(t, bLo, n0 + j * 16, kb, lane);
            bl[2 * j][0] = t[0]; bl[2 * j][1] = t[2];
            bl[2 * j + 1][0] = t[1]; bl[2 * j + 1][1] = t[3];
        }
#pragma unroll
        for (int m = 0; m < 2; m++)
#pragma unroll
            for (int n = 0; n < 8; n++) {
                mma16(acc[m][n], ah[m], bh[n]);
                mma16(acc[m][n], ah[m], bl[n]);
                mma16(acc[m][n], al[m], bh[n]);
            }
    }
}

#define ZERO8(acc) \
    { _Pragma("unroll") for (int m = 0; m < 2; m++) \
      _Pragma("unroll") for (int n = 0; n < 8; n++) \
      _Pragma("unroll") for (int v = 0; v < 4; v++) acc[m][n][v] = 0.f; }

#define PSTAGE 24576
#define BSTAGE 16384
#define NSTG   3
#define ASLOTOFF 49152
#define BATTOFF  73728
#define ATTN_SMEM 106496

// ---------------- fused prepass (unchanged, 256 thr) ----------------
#define WCTAS 576
__global__ void prepass_kernel(const float* __restrict__ w, const float* __restrict__ ctx) {
    __shared__ float t[32][33];
    const int bid = blockIdx.x, tid = threadIdx.x;
    if (bid < WCTAS) {
        int i4 = bid * 256 + tid;
        float4 v = reinterpret_cast<const float4*>(w)[i4];
        __nv_bfloat16 h0, l0, h1, l1, h2, l2, h3, l3;
        split2(v.x, h0, l0); split2(v.y, h1, l1);
        split2(v.z, h2, l2); split2(v.w, h3, l3);
        reinterpret_cast<uint2*>(g_w_hi)[i4] = make_uint2(pack_bf2(h0, h1), pack_bf2(h2, h3));
        reinterpret_cast<uint2*>(g_w_lo)[i4] = make_uint2(pack_bf2(l0, l1), pack_bf2(l2, l3));
        return;
    }
    const int g = bid - WCTAS;
    const int b = g / 96, rem = g % 96;
    const int c0 = (rem >> 2) * 32, s0 = (rem & 3) * 32;
    const int x = tid & 31, y = tid >> 5;
#pragma unroll
    for (int r = 0; r < 32; r += 8)
        t[y + r][x] = ctx[((size_t)b * CDF + c0 + y + r) * SL + s0 + x];
    __syncthreads();
#pragma unroll
    for (int r = 0; r < 32; r += 8) {
        size_t o = ((size_t)b * SL + s0 + y + r) * CDF + c0 + x;
        __nv_bfloat16 h, l; split2(t[x][y + r], h, l);
        g_ctxT_hi[o] = h; g_ctxT_lo[o] = l;
    }
}

// ---------------- proj: 64(o) x 128(s), 128 thr, warp tile 32x64 ----------------
__global__ void __launch_bounds__(128, 2) proj_kernel() {
    extern __shared__ __align__(1024) char smem[];
    const int tid = threadIdx.x, lane = tid & 31, wp = tid >> 5;
    const int wm = wp & 1, wn = wp >> 1;                     // 2m x 2n warps
    const int b = blockIdx.y, o0 = blockIdx.x * 64;
    uint32_t sb = smem_u32(smem);
    float* Cb = reinterpret_cast<float*>(smem);              // [64][129], aliases stages

    const __nv_bfloat16* wh_base = g_w_hi + (size_t)o0 * CDF;
    const __nv_bfloat16* wl_base = g_w_lo + (size_t)o0 * CDF;
    const __nv_bfloat16* ch_base = g_ctxT_hi + (size_t)b * SL * CDF;
    const __nv_bfloat16* cl_base = g_ctxT_lo + (size_t)b * SL * CDF;

    float acc[2][8][4];
    ZERO8(acc);

    auto issue = [&](int j) {
        uint32_t S = sb + (j % NSTG) * PSTAGE;
        cp64<64, 128>(S,          wh_base + j * 32, CDF * 2, tid);
        cp64<64, 128>(S + 4096,   wl_base + j * 32, CDF * 2, tid);
        cp64<128, 128>(S + 8192,  ch_base + j * 32, CDF * 2, tid);
        cp64<128, 128>(S + 16384, cl_base + j * 32, CDF * 2, tid);
        CP_COMMIT();
    };
    issue(0); issue(1);
#pragma unroll 1
    for (int j = 0; j < 24; j++) {
        if (j < 23) CP_WAIT1(); else CP_WAIT0();
        __syncthreads();
        if (j + 2 < 24) issue(j + 2);
        uint32_t S = sb + (j % NSTG) * PSTAGE;
        gemm64(acc, S, S + 4096, S + 8192, S + 16384, wm * 32, wn * 64, lane);
    }
    __syncthreads();

    // pass 1: sis direct from fragments + Cb stage
    {
        __nv_bfloat16* sh = g_sis_hi + ((size_t)b * IDF + o0) * SL;
        __nv_bfloat16* sl = g_sis_lo + ((size_t)b * IDF + o0) * SL;
#pragma unroll
        for (int m = 0; m < 2; m++)
#pragma unroll
            for (int h = 0; h < 2; h++) {
                const int o = wm * 32 + m * 16 + (lane >> 2) + h * 8;
#pragma unroll
                for (int n = 0; n < 8; n++) {
                    float v0 = acc[m][n][h * 2 + 0];
                    float v1 = acc[m][n][h * 2 + 1];
                    const int s = wn * 64 + n * 8 + (lane & 3) * 2;
                    Cb[o * 129 + s]     = v0;
                    Cb[o * 129 + s + 1] = v1;
                    __nv_bfloat16 h0, l0, h1, l1;
                    split2(v0, h0, l0); split2(v1, h1, l1);
                    *reinterpret_cast<uint32_t*>(sh + (size_t)o * SL + s) = pack_bf2(h0, h1);
                    *reinterpret_cast<uint32_t*>(sl + (size_t)o * SL + s) = pack_bf2(l0, l1);
                }
            }
    }
    __syncthreads();

    // pass 2: ssi transpose via Cb; thread = one s row, 64 o in 2 halves
    {
        const int s = tid;
#pragma unroll
        for (int half = 0; half < 2; half++) {
            uint32_t uh[16], ul[16];
#pragma unroll
            for (int m = 0; m < 16; m++) {
                float v0 = Cb[(half * 32 + 2 * m) * 129 + s];
                float v1 = Cb[(half * 32 + 2 * m + 1) * 129 + s];
                __nv_bfloat16 h0, l0, h1, l1; split2(v0, h0, l0); split2(v1, h1, l1);
                uh[m] = pack_bf2(h0, h1); ul[m] = pack_bf2(l0, l1);
            }
            size_t off = ((size_t)b * SL + s) * IDF + o0 + half * 32;
#pragma unroll
            for (int m = 0; m < 4; m++) {
                reinterpret_cast<uint4*>(g_ssi_hi + off)[m] =
                    make_uint4(uh[4 * m], uh[4 * m + 1], uh[4 * m + 2], uh[4 * m + 3]);
                reinterpret_cast<uint4*>(g_ssi_lo + off)[m] =
                    make_uint4(ul[4 * m], ul[4 * m + 1], ul[4 * m + 2], ul[4 * m + 3]);
            }
        }
    }
}

// ---------------- fused attention: 128 thr, warp tile 32x64, register softmax ----------------
__global__ void __launch_bounds__(128, 2) attn_kernel(const float* __restrict__ input,
                                                      const int* __restrict__ mask,
                                                      float* __restrict__ wc,
                                                      float* __restrict__ aout) {
    extern __shared__ __align__(1024) char smem[];
    __shared__ float red[64][2];
    const int tid = threadIdx.x, lane = tid & 31, wp = tid >> 5;
    const int b = blockIdx.y, q0 = blockIdx.x * 64;
    uint32_t sb = smem_u32(smem);
    const uint32_t ASLOT = sb + ASLOTOFF;
    const uint32_t BATT  = sb + BATTOFF;

    const int wm1 = wp & 1, wn1 = wp >> 1;          // D 64q x 128s, warps 2m x 2n
    const __nv_bfloat16* sh_base = g_ssi_hi + (size_t)b * SL * IDF;
    const __nv_bfloat16* sl_base = g_ssi_lo + (size_t)b * SL * IDF;
    const int cq = tid & 63, cig = tid >> 6;        // conversion: 2 groups of 16 i
    const float* cbase = input + ((size_t)b * IDF + cig * 16) * QL + q0 + cq;
    const uint32_t coff  = SW64((uint32_t)(cq * 64 + cig * 32));
    const uint32_t coff2 = SW64((uint32_t)(cq * 64 + cig * 32 + 16));

    float acc[2][8][4];
    ZERO8(acc);
    float cvt[16];

    auto ldgA = [&](int j) {
        const float* s = cbase + (size_t)(j * 32) * QL;
#pragma unroll
        for (int m = 0; m < 16; m++) cvt[m] = s[(size_t)m * QL];
    };
    auto stsA = [&](int j) {
        uint32_t h[8], l[8];
#pragma unroll
        for (int m = 0; m < 8; m++) {
            __nv_bfloat16 h0, l0, h1, l1;
            split2(cvt[2 * m], h0, l0); split2(cvt[2 * m + 1], h1, l1);
            h[m] = pack_bf2(h0, h1); l[m] = pack_bf2(l0, l1);
        }
        uint32_t A = ASLOT + (j % 3) * 8192;
        asm volatile("st.shared.v4.b32 [%0], {%1,%2,%3,%4};"
                     :: "r"(A + coff), "r"(h[0]), "r"(h[1]), "r"(h[2]), "r"(h[3]));
        asm volatile("st.shared.v4.b32 [%0], {%1,%2,%3,%4};"
                     :: "r"(A + coff2), "r"(h[4]), "r"(h[5]), "r"(h[6]), "r"(h[7]));
        asm volatile("st.shared.v4.b32 [%0], {%1,%2,%3,%4};"
                     :: "r"(A + 4096 + coff), "r"(l[0]), "r"(l[1]), "r"(l[2]), "r"(l[3]));
        asm volatile("st.shared.v4.b32 [%0], {%1,%2,%3,%4};"
                     :: "r"(A + 4096 + coff2), "r"(l[4]), "r"(l[5]), "r"(l[6]), "r"(l[7]));
    };
    auto issueB = [&](int j) {
        uint32_t S = sb + (j % NSTG) * BSTAGE;
        cp64<128, 128>(S,        sh_base + j * 32, IDF * 2, tid);
        cp64<128, 128>(S + 8192, sl_base + j * 32, IDF * 2, tid);
        CP_COMMIT();
    };

    ldgA(0); stsA(0); ldgA(1);
    issueB(0); issueB(1);
#pragma unroll 1
    for (int j = 0; j < 24; j++) {
        if (j + 1 < 24) stsA(j + 1);
        if (j + 2 < 24) ldgA(j + 2);
        if (j < 23) CP_WAIT1(); else CP_WAIT0();
        __syncthreads();
        if (j + 2 < 24) issueB(j + 2);
        uint32_t S = sb + (j % NSTG) * BSTAGE;
        uint32_t A = ASLOT + (j % 3) * 8192;
        gemm64(acc, A, A + 4096, S, S + 8192, wm1 * 32, wn1 * 64, lane);
    }
    __syncthreads();

    const __nv_bfloat16* sish_base = g_sis_hi + (size_t)b * IDF * SL;
    const __nv_bfloat16* sisl_base = g_sis_lo + (size_t)b * IDF * SL;
    auto issue3 = [&](int c) {
        int t = c >> 2, kc = c & 3;
        uint32_t S = sb + (c % NSTG) * BSTAGE;
        const size_t base = (size_t)t * 128 * SL + kc * 32;
        cp64<128, 128>(S,        sish_base + base, SL * 2, tid);
        cp64<128, 128>(S + 8192, sisl_base + base, SL * 2, tid);
        CP_COMMIT();
    };
    issue3(0); issue3(1);

    // phase 2: softmax entirely in registers; cols s = wn1*64 + n*8 + (lane&3)*2 + vi
    {
        float mp[16];
#pragma unroll
        for (int n = 0; n < 8; n++)
#pragma unroll
            for (int vi = 0; vi < 2; vi++)
                mp[n * 2 + vi] = -10000.0f *
                    (float)mask[b * SL + wn1 * 64 + n * 8 + (lane & 3) * 2 + vi];

        float mx4[4];
#pragma unroll
        for (int mi = 0; mi < 2; mi++)
#pragma unroll
            for (int h = 0; h < 2; h++) {
                float mx = -1e30f;
#pragma unroll
                for (int n = 0; n < 8; n++)
#pragma unroll
                    for (int vi = 0; vi < 2; vi++) {
                        int v = h * 2 + vi;
                        acc[mi][n][v] += mp[n * 2 + vi];
                        mx = fmaxf(mx, acc[mi][n][v]);
                    }
                mx4[mi * 2 + h] = mx;
            }
#pragma unroll
        for (int r = 0; r < 4; r++) {
            mx4[r] = fmaxf(mx4[r], __shfl_xor_sync(0xffffffffu, mx4[r], 1));
            mx4[r] = fmaxf(mx4[r], __shfl_xor_sync(0xffffffffu, mx4[r], 2));
        }
        if ((lane & 3) == 0)
#pragma unroll
            for (int r = 0; r < 4; r++)
                red[wm1 * 32 + (r >> 1) * 16 + (lane >> 2) + (r & 1) * 8][wn1] = mx4[r];
        __syncthreads();
#pragma unroll
        for (int r = 0; r < 4; r++) {
            const float* rr = red[wm1 * 32 + (r >> 1) * 16 + (lane >> 2) + (r & 1) * 8];
            mx4[r] = fmaxf(rr[0], rr[1]);
        }
        __syncthreads();

        float sm4[4];
#pragma unroll
        for (int mi = 0; mi < 2; mi++)
#pragma unroll
            for (int h = 0; h < 2; h++) {
                float sum = 0.f;
#pragma unroll
                for (int n = 0; n < 8; n++)
#pragma unroll
                    for (int vi = 0; vi < 2; vi++) {
                        int v = h * 2 + vi;
                        float e = __expf(acc[mi][n][v] - mx4[mi * 2 + h]);
                        acc[mi][n][v] = e;
                        sum += e;
                    }
                sm4[mi * 2 + h] = sum;
            }
#pragma unroll
        for (int r = 0; r < 4; r++) {
            sm4[r] += __shfl_xor_sync(0xffffffffu, sm4[r], 1);
            sm4[r] += __shfl_xor_sync(0xffffffffu, sm4[r], 2);
        }
        if ((lane & 3) == 0)
#pragma unroll
            for (int r = 0; r < 4; r++)
                red[wm1 * 32 + (r >> 1) * 16 + (lane >> 2) + (r & 1) * 8][wn1] = sm4[r];
        __syncthreads();
#pragma unroll
        for (int r = 0; r < 4; r++) {
            const float* rr = red[wm1 * 32 + (r >> 1) * 16 + (lane >> 2) + (r & 1) * 8];
            sm4[r] = 1.0f / (rr[0] + rr[1]);
        }

        float* ao = aout + (size_t)b * SL * QL + q0;
#pragma unroll
        for (int mi = 0; mi < 2; mi++)
#pragma unroll
            for (int h = 0; h < 2; h++) {
                const float inv = sm4[mi * 2 + h];
                const int q = wm1 * 32 + mi * 16 + (lane >> 2) + h * 8;
#pragma unroll
                for (int n = 0; n < 8; n++) {
                    float e0 = acc[mi][n][h * 2 + 0] * inv;
                    float e1 = acc[mi][n][h * 2 + 1] * inv;
                    const int s0 = wn1 * 64 + n * 8 + (lane & 3) * 2;
                    ao[(size_t)s0 * QL + q]       = e0;
                    ao[(size_t)(s0 + 1) * QL + q] = e1;
                    __nv_bfloat16 h0, l0, h1, l1;
                    split2(e0, h0, l0); split2(e1, h1, l1);
                    uint32_t BH = BATT + (uint32_t)(s0 >> 5) * 8192;
                    uint32_t off = SW64((uint32_t)(q * 64 + (s0 & 31) * 2));
                    asm volatile("st.shared.b32 [%0], %1;"
                                 :: "r"(BH + off), "r"(pack_bf2(h0, h1)));
                    asm volatile("st.shared.b32 [%0], %1;"
                                 :: "r"(BH + 4096 + off), "r"(pack_bf2(l0, l1)));
                }
            }
    }
    __syncthreads();

    // phase 3: D 128i x 64q; warp wp -> 32 i rows, full 64 q
#pragma unroll 1
    for (int c = 0; c < 24; c++) {
        if (c < 23) CP_WAIT1(); else CP_WAIT0();
        __syncthreads();
        if (c + 2 < 24) issue3(c + 2);
        if ((c & 3) == 0) ZERO8(acc);
        uint32_t S = sb + (c % NSTG) * BSTAGE;
        uint32_t BH = BATT + (c & 3) * 8192;
        gemm64(acc, S, S + 8192, BH, BH + 4096, wp * 32, 0, lane);
        if ((c & 3) == 3) {
            int t = c >> 2;
            float* w0 = wc + ((size_t)b * IDF + t * 128) * QL + q0;
#pragma unroll
            for (int m = 0; m < 2; m++)
#pragma unroll
                for (int n = 0; n < 8; n++) {
                    int r = wp * 32 + m * 16 + (lane >> 2);
                    int cc = n * 8 + (lane & 3) * 2;
                    *reinterpret_cast<float2*>(w0 + (size_t)r * QL + cc) =
                        make_float2(acc[m][n][0], acc[m][n][1]);
                    *reinterpret_cast<float2*>(w0 + (size_t)(r + 8) * QL + cc) =
                        make_float2(acc[m][n][2], acc[m][n][3]);
                }
        }
    }
}

// ---------------------------------------------------------------------------
extern "C" void kernel_launch(void* const* d_in, const int* in_sizes, int n_in,
                              void* d_out, int out_size) {
    const float* input   = (const float*)d_in[0];
    const float* context = (const float*)d_in[1];
    const int*   mask    = (const int*)d_in[2];
    const float* w_conv  = (const float*)d_in[3];

    float* wc   = (float*)d_out;
    float* aout = wc + (size_t)NB * IDF * QL;

    prepass_kernel<<<WCTAS + NB * 96, 256>>>(w_conv, context);

    const int smem_proj = NSTG * PSTAGE;                    // 73728
    cudaFuncSetAttribute(proj_kernel, cudaFuncAttributeMaxDynamicSharedMemorySize,
                         smem_proj);
    proj_kernel<<<dim3(IDF / 64, NB), 128, smem_proj>>>();

    cudaFuncSetAttribute(attn_kernel, cudaFuncAttributeMaxDynamicSharedMemorySize,
                         ATTN_SMEM);                        // 106496
    attn_kernel<<<dim3(QL / 64, NB), 128, ATTN_SMEM>>>(input, mask, wc, aout);
}